// round 14
// baseline (speedup 1.0000x reference)
#include <cuda_runtime.h>
#include <float.h>
#include <stdint.h>

#define N_NODES 50000
#define DEG     32
#define WID     128
#define BATCH   4096
#define NT      256
#define TM      64           // tile rows (all tensor kernels)
#define APLD    66           // A-pair ld (uint2 units)
#define WLD     130          // Ws ld (uint2 units)
#define WSP     16           // weight pairs per stage (4 stages per GEMM)
#define NPAIR   64           // k-pairs per weight matrix

// ---------------- device scratch ----------------
// g_winner: slot+1 of last batch write, 0 = not in batch (zero-init; k_agg2 self-cleans)
__device__ int   g_winner[N_NODES];
__device__ float g_Mb[BATCH * WID];
__device__ float g_Fh[BATCH * WID];
__device__ float g_H1[N_NODES * WID];
__device__ float g_M2[N_NODES * WID];
__device__ float g_A2[BATCH * WID];
__device__ uint2 g_Wa2[NPAIR * WID];    // [kpair][n] bf16x2 {hi,lo}: low16 = even k
__device__ uint2 g_Wla2[NPAIR * WID];
__device__ uint2 g_Wlh2[NPAIR * WID];

// ---------------- bf16 split helpers ----------------
__device__ __forceinline__ void bfsplit2(float2 f, uint32_t& hi, uint32_t& lo) {
    uint32_t h;
    asm("cvt.rn.bf16x2.f32 %0, %1, %2;" : "=r"(h) : "f"(f.y), "f"(f.x));  // d<15:0>=f.x
    float h0 = __uint_as_float(h << 16);
    float h1 = __uint_as_float(h & 0xffff0000u);
    float r0 = f.x - h0, r1 = f.y - h1;
    asm("cvt.rn.bf16x2.f32 %0, %1, %2;" : "=r"(lo) : "f"(r1), "f"(r0));
    hi = h;
}

// m16n8k16 bf16 mma (fragment coords validated R12).
__device__ __forceinline__ void mma16(float* c, const uint32_t* a, uint32_t b0, uint32_t b1) {
    asm volatile(
        "mma.sync.aligned.m16n8k16.row.col.f32.bf16.bf16.f32 "
        "{%0,%1,%2,%3},{%4,%5,%6,%7},{%8,%9},{%0,%1,%2,%3};"
        : "+f"(c[0]), "+f"(c[1]), "+f"(c[2]), "+f"(c[3])
        : "r"(a[0]), "r"(a[1]), "r"(a[2]), "r"(a[3]), "r"(b0), "r"(b1));
}

__device__ __forceinline__ void zeroC(float C[8][4]) {
#pragma unroll
    for (int j = 0; j < 8; ++j)
#pragma unroll
        for (int c = 0; c < 4; ++c) C[j][c] = 0.f;
}

// ---------------- shared tensor GEMM: 64x128x128, 16-pair weight stages ----------------
// Apk: smem [row][kpair] uint2{hi,lo}. gW: global presplit [kpair][n].
// 8 warps: mw = warp>>1 (16 rows), nw = warp&1 (64 cols). C[8 nblk][4]. Accumulates.
__device__ __forceinline__ void tgemm(const uint2* __restrict__ Apk,
                                      const uint2* __restrict__ gW,
                                      uint2* Ws, float C[8][4],
                                      int mw, int nw, int lane) {
    const int g = lane >> 2, t = lane & 3;
#pragma unroll 1
    for (int q = 0; q < 4; ++q) {               // four 32-k stages (16 pairs each)
        for (int e = threadIdx.x; e < WSP * 64; e += NT) {
            int p = e >> 6, n2 = (e & 63) << 1;
            *(uint4*)(Ws + p * WLD + n2) = *(const uint4*)(gW + (q * WSP + p) * WID + n2);
        }
        __syncthreads();
#pragma unroll
        for (int ks = 0; ks < 2; ++ks) {        // 2 x k16 per stage
            int pk = q * WSP + ks * 8;
            const uint2* ap0 = Apk + (mw * 16 + g) * APLD + pk + t;
            const uint2* ap1 = ap0 + 8 * APLD;
            uint2 p0 = ap0[0], p1 = ap1[0], p2 = ap0[4], p3 = ap1[4];
            uint32_t ahi[4] = { p0.x, p1.x, p2.x, p3.x };
            uint32_t alo[4] = { p0.y, p1.y, p2.y, p3.y };
            const uint2* bp0 = Ws + (ks * 8 + t) * WLD + nw * 64 + g;
            const uint2* bp1 = bp0 + 4 * WLD;
#pragma unroll
            for (int j = 0; j < 8; ++j) {
                uint2 b0 = bp0[j * 8];
                uint2 b1 = bp1[j * 8];
                mma16(C[j], ahi, b0.y, b1.y);   // hi * lo
                mma16(C[j], alo, b0.x, b1.x);   // lo * hi
                mma16(C[j], ahi, b0.x, b1.x);   // hi * hi
            }
        }
        __syncthreads();
    }
}

// ---------------- setup: weight presplit + winner scatter (one kernel) ----------------
__global__ void k_prep(const float* __restrict__ W_agg, const float* __restrict__ W_lin,
                       const int* __restrict__ node_idx) {
    int t = blockIdx.x * NT + threadIdx.x;
    if (t < NPAIR * WID) {                      // kpair p: k = 2p, 2p+1
        int p = t >> 7, n = t & 127;
        uint32_t hi, lo;
        float2 fa = make_float2(W_agg[n * WID + 2 * p], W_agg[n * WID + 2 * p + 1]);
        bfsplit2(fa, hi, lo);
        g_Wa2[t] = make_uint2(hi, lo);
        float2 fh = make_float2(W_lin[n * (2 * WID) + 2 * p],
                                W_lin[n * (2 * WID) + 2 * p + 1]);
        bfsplit2(fh, hi, lo);
        g_Wlh2[t] = make_uint2(hi, lo);
        float2 fl = make_float2(W_lin[n * (2 * WID) + WID + 2 * p],
                                W_lin[n * (2 * WID) + WID + 2 * p + 1]);
        bfsplit2(fl, hi, lo);
        g_Wla2[t] = make_uint2(hi, lo);
    }
    if (t < BATCH) atomicMax(&g_winner[node_idx[t]], t + 1);   // slot+1 sentinel
}

// ---------------- batch precompute: Mb and Fh (tensor path) ----------------
#define BATCH_SMEM ((TM * APLD + WSP * WLD) * 8)
__global__ void __launch_bounds__(NT, 2)
k_batch(const float* __restrict__ feats, const float* __restrict__ b_agg) {
    extern __shared__ float sm[];
    uint2* Apk = (uint2*)sm;
    uint2* Ws  = Apk + TM * APLD;
    const int tid = threadIdx.x, lane = tid & 31, warp = tid >> 5;
    const int mw = warp >> 1, nw = warp & 1;
    const int g = lane >> 2, t4 = lane & 3;
    const int r0 = blockIdx.x * TM;

    for (int e = tid; e < TM * 64; e += NT) {
        int row = e >> 6, p = e & 63;
        float2 f = *(const float2*)(feats + (r0 + row) * WID + 2 * p);
        uint32_t hi, lo;
        bfsplit2(f, hi, lo);
        Apk[row * APLD + p] = make_uint2(hi, lo);
    }
    // (tgemm's first stage-sync orders Apk writes before reads)

    float C[8][4];
    zeroC(C);
    tgemm(Apk, g_Wa2, Ws, C, mw, nw, lane);

    float2 ba[8];
#pragma unroll
    for (int j = 0; j < 8; ++j)
        ba[j] = *(const float2*)(b_agg + nw * 64 + j * 8 + 2 * t4);
#pragma unroll
    for (int h = 0; h < 2; ++h) {
        int row = r0 + mw * 16 + g + 8 * h;
#pragma unroll
        for (int j = 0; j < 8; ++j) {
            float v0 = fmaxf(C[j][2 * h] + ba[j].x, 0.f);
            float v1 = fmaxf(C[j][2 * h + 1] + ba[j].y, 0.f);
            *(float2*)(g_Mb + row * WID + nw * 64 + j * 8 + 2 * t4) = make_float2(v0, v1);
        }
    }

    zeroC(C);
    tgemm(Apk, g_Wlh2, Ws, C, mw, nw, lane);
#pragma unroll
    for (int h = 0; h < 2; ++h) {
        int row = r0 + mw * 16 + g + 8 * h;
#pragma unroll
        for (int j = 0; j < 8; ++j)
            *(float2*)(g_Fh + row * WID + nw * 64 + j * 8 + 2 * t4) =
                make_float2(C[j][2 * h], C[j][2 * h + 1]);
    }
}

// ---------------- main fused: layer1 (agg+combine+norm) + layer2 M2 ----------------
#define MAIN_SMEM ((TM * APLD + WSP * WLD) * 8 + 2 * TM * 4)
__global__ void __launch_bounds__(NT, 4)
k_main(const int* __restrict__ nbd, const float* __restrict__ b_agg,
       const float* __restrict__ b_lin) {
    extern __shared__ float sm[];
    uint2* Apk = (uint2*)sm;                      // [64][66] {hi,lo} pairs
    uint2* Ws  = Apk + TM * APLD;                 // [16 pairs][130]
    float* ps  = (float*)(Ws + WSP * WLD);        // [2][64]
    const int tid = threadIdx.x, lane = tid & 31, warp = tid >> 5;
    const int mw = warp >> 1, nw = warp & 1;
    const int g = lane >> 2, t4 = lane & 3;
    const int r0 = blockIdx.x * TM;

    // cvec pairs: lane owns dim pairs (2*lane, 2*lane+1) and (64+2*lane, +1)
    float2 bg0 = *(const float2*)(b_agg + 2 * lane);
    float2 bg1 = *(const float2*)(b_agg + 64 + 2 * lane);
    float2 cv0 = make_float2(fmaxf(bg0.x, 0.f), fmaxf(bg0.y, 0.f));
    float2 cv1 = make_float2(fmaxf(bg1.x, 0.f), fmaxf(bg1.y, 0.f));

    // phase A: sparse max-aggregation -> split directly into Apk
#pragma unroll 1
    for (int t = warp; t < TM; t += 8) {
        int gn = r0 + t;                          // warp-uniform
        float2 a0 = make_float2(0.f, 0.f), a1 = make_float2(0.f, 0.f);
        if (gn < N_NODES) {
            int nb = nbd[gn * DEG + lane];
            int wv = g_winner[nb];                // slot+1, 0 = absent
            unsigned mask = __ballot_sync(0xffffffffu, wv > 0);
            bool plain = (mask != 0xffffffffu);
            a0 = plain ? cv0 : make_float2(-FLT_MAX, -FLT_MAX);
            a1 = plain ? cv1 : make_float2(-FLT_MAX, -FLT_MAX);
            while (mask) {
                int j = __ffs(mask) - 1;
                mask &= mask - 1;
                int wj = __shfl_sync(0xffffffffu, wv, j) - 1;
                const float* mb = g_Mb + wj * WID;
                float2 m0 = *(const float2*)(mb + 2 * lane);
                float2 m1 = *(const float2*)(mb + 64 + 2 * lane);
                a0.x = fmaxf(a0.x, m0.x); a0.y = fmaxf(a0.y, m0.y);
                a1.x = fmaxf(a1.x, m1.x); a1.y = fmaxf(a1.y, m1.y);
            }
        }
        uint32_t hi, lo;
        bfsplit2(a0, hi, lo);
        Apk[t * APLD + lane] = make_uint2(hi, lo);
        bfsplit2(a1, hi, lo);
        Apk[t * APLD + 32 + lane] = make_uint2(hi, lo);
    }
    // (tgemm's first stage-sync orders Apk writes before reads)

    // GEMM 1: agg @ Wla^T
    float C[8][4];
    zeroC(C);
    tgemm(Apk, g_Wla2, Ws, C, mw, nw, lane);

    // epilogue 1: + b_lin (+Fh winner), relu, row sumsq -> ps
    float2 bl[8];
#pragma unroll
    for (int j = 0; j < 8; ++j)
        bl[j] = *(const float2*)(b_lin + nw * 64 + j * 8 + 2 * t4);
    int warr[2];
#pragma unroll
    for (int h = 0; h < 2; ++h) {
        int rloc = mw * 16 + g + 8 * h;
        int gn = r0 + rloc;
        int w = (gn < N_NODES) ? g_winner[gn] : 0;
        warr[h] = w;
        float s = 0.f;
#pragma unroll
        for (int j = 0; j < 8; ++j) {
            float v0 = C[j][2 * h] + bl[j].x;
            float v1 = C[j][2 * h + 1] + bl[j].y;
            if (w > 0) {
                float2 f = *(const float2*)(g_Fh + (w - 1) * WID + nw * 64 + j * 8 + 2 * t4);
                v0 += f.x; v1 += f.y;
            }
            v0 = fmaxf(v0, 0.f); v1 = fmaxf(v1, 0.f);
            s += v0 * v0 + v1 * v1;
            C[j][2 * h] = v0; C[j][2 * h + 1] = v1;
        }
        s += __shfl_xor_sync(0xffffffffu, s, 1);
        s += __shfl_xor_sync(0xffffffffu, s, 2);
        if (t4 == 0) ps[nw * TM + rloc] = s;
    }
    __syncthreads();
    // normalize, stage H1 pairs into Apk, write H1 global for winner rows
#pragma unroll
    for (int h = 0; h < 2; ++h) {
        int rloc = mw * 16 + g + 8 * h;
        int gn = r0 + rloc;
        float t = ps[rloc] + ps[TM + rloc];
        float rinv = 1.0f / fmaxf(sqrtf(t), 1e-12f);
        int w = warr[h];
#pragma unroll
        for (int j = 0; j < 8; ++j) {
            float v0 = C[j][2 * h] * rinv;
            float v1 = C[j][2 * h + 1] * rinv;
            uint32_t hi, lo;
            bfsplit2(make_float2(v0, v1), hi, lo);
            Apk[rloc * APLD + nw * 32 + j * 4 + t4] = make_uint2(hi, lo);
            if (w > 0)
                *(float2*)(g_H1 + gn * WID + nw * 64 + j * 8 + 2 * t4) = make_float2(v0, v1);
        }
    }

    // GEMM 2: M2 = relu(H1 @ Wa^T + ba)
    zeroC(C);
    tgemm(Apk, g_Wa2, Ws, C, mw, nw, lane);      // stage-sync orders Apk writes

    float2 ba[8];
#pragma unroll
    for (int j = 0; j < 8; ++j)
        ba[j] = *(const float2*)(b_agg + nw * 64 + j * 8 + 2 * t4);
#pragma unroll
    for (int h = 0; h < 2; ++h) {
        int rloc = mw * 16 + g + 8 * h;
        int gn = r0 + rloc;
        if (gn >= N_NODES) continue;
#pragma unroll
        for (int j = 0; j < 8; ++j) {
            float v0 = fmaxf(C[j][2 * h] + ba[j].x, 0.f);
            float v1 = fmaxf(C[j][2 * h + 1] + ba[j].y, 0.f);
            *(float2*)(g_M2 + gn * WID + nw * 64 + j * 8 + 2 * t4) = make_float2(v0, v1);
        }
    }
}

// ---------------- layer-2 aggregation (+ winner cleanup for next launch) ----------------
__global__ void __launch_bounds__(NT, 4)
k_agg2(const int* __restrict__ nbd, const int* __restrict__ node_idx) {
    const int lane = threadIdx.x & 31, warp = threadIdx.x >> 5;
    const int slot = blockIdx.x * 8 + warp;
    const int gn = node_idx[slot];
    if (lane == 0) g_winner[gn] = 0;             // self-clean (winner last used in k_main)
    int nb = nbd[gn * DEG + lane];
    float4 acc = make_float4(-FLT_MAX, -FLT_MAX, -FLT_MAX, -FLT_MAX);
#pragma unroll 1
    for (int j = 0; j < DEG; ++j) {
        int nbj = __shfl_sync(0xffffffffu, nb, j);
        float4 m = *(const float4*)(g_M2 + nbj * WID + lane * 4);
        acc.x = fmaxf(acc.x, m.x); acc.y = fmaxf(acc.y, m.y);
        acc.z = fmaxf(acc.z, m.z); acc.w = fmaxf(acc.w, m.w);
    }
    *(float4*)(g_A2 + slot * WID + lane * 4) = acc;
}

// ---------------- layer 2 final: 256-K tensor combine + norm ----------------
#define L2F_SMEM ((2 * TM * APLD + WSP * WLD) * 8 + 2 * TM * 4 + TM * 4)
__global__ void __launch_bounds__(NT, 2)
k_l2f(const int* __restrict__ node_idx, const float* __restrict__ b_lin,
      float* __restrict__ out) {
    extern __shared__ float sm[];
    uint2* A1 = (uint2*)sm;
    uint2* A2 = A1 + TM * APLD;
    uint2* Ws = A2 + TM * APLD;
    float* ps = (float*)(Ws + WSP * WLD);
    int*   nid = (int*)(ps + 2 * TM);
    const int tid = threadIdx.x, lane = tid & 31, warp = tid >> 5;
    const int mw = warp >> 1, nw = warp & 1;
    const int g = lane >> 2, t4 = lane & 3;
    const int r0 = blockIdx.x * TM;

    if (tid < TM) nid[tid] = node_idx[r0 + tid];
    __syncthreads();

    for (int e = tid; e < TM * 64; e += NT) {
        int row = e >> 6, p = e & 63;
        uint32_t hi, lo;
        float2 f = *(const float2*)(g_H1 + nid[row] * WID + 2 * p);
        bfsplit2(f, hi, lo);
        A1[row * APLD + p] = make_uint2(hi, lo);
        float2 a = *(const float2*)(g_A2 + (r0 + row) * WID + 2 * p);
        bfsplit2(a, hi, lo);
        A2[row * APLD + p] = make_uint2(hi, lo);
    }
    // (tgemm's first stage-sync orders A1/A2 writes before reads)

    float C[8][4];
    zeroC(C);
    tgemm(A1, g_Wlh2, Ws, C, mw, nw, lane);
    tgemm(A2, g_Wla2, Ws, C, mw, nw, lane);      // accumulate second K-half

    float2 bl[8];
#pragma unroll
    for (int j = 0; j < 8; ++j)
        bl[j] = *(const float2*)(b_lin + nw * 64 + j * 8 + 2 * t4);
#pragma unroll
    for (int h = 0; h < 2; ++h) {
        int rloc = mw * 16 + g + 8 * h;
        float s = 0.f;
#pragma unroll
        for (int j = 0; j < 8; ++j) {
            float v0 = fmaxf(C[j][2 * h] + bl[j].x, 0.f);
            float v1 = fmaxf(C[j][2 * h + 1] + bl[j].y, 0.f);
            s += v0 * v0 + v1 * v1;
            C[j][2 * h] = v0; C[j][2 * h + 1] = v1;
        }
        s += __shfl_xor_sync(0xffffffffu, s, 1);
        s += __shfl_xor_sync(0xffffffffu, s, 2);
        if (t4 == 0) ps[nw * TM + rloc] = s;
    }
    __syncthreads();
#pragma unroll
    for (int h = 0; h < 2; ++h) {
        int rloc = mw * 16 + g + 8 * h;
        float t = ps[rloc] + ps[TM + rloc];
        float rinv = 1.0f / fmaxf(sqrtf(t), 1e-12f);
#pragma unroll
        for (int j = 0; j < 8; ++j) {
            float v0 = C[j][2 * h] * rinv;
            float v1 = C[j][2 * h + 1] * rinv;
            *(float2*)(out + (r0 + rloc) * WID + nw * 64 + j * 8 + 2 * t4) =
                make_float2(v0, v1);
        }
    }
}

// ---------------- launch ----------------
extern "C" void kernel_launch(void* const* d_in, const int* in_sizes, int n_in,
                              void* d_out, int out_size) {
    const int*   nbd      = (const int*)d_in[0];
    const int*   node_idx = (const int*)d_in[1];
    const float* feats    = (const float*)d_in[2];
    const float* W_agg    = (const float*)d_in[3];
    const float* b_agg    = (const float*)d_in[4];
    const float* W_lin    = (const float*)d_in[5];
    const float* b_lin    = (const float*)d_in[6];
    float* out = (float*)d_out;

    cudaFuncSetAttribute(k_batch, cudaFuncAttributeMaxDynamicSharedMemorySize, BATCH_SMEM);
    cudaFuncSetAttribute(k_main,  cudaFuncAttributeMaxDynamicSharedMemorySize, MAIN_SMEM);
    cudaFuncSetAttribute(k_l2f,   cudaFuncAttributeMaxDynamicSharedMemorySize, L2F_SMEM);

    k_prep<<<(NPAIR * WID + NT - 1) / NT, NT>>>(W_agg, W_lin, node_idx);
    k_batch<<<BATCH / TM, NT, BATCH_SMEM>>>(feats, b_agg);
    k_main<<<(N_NODES + TM - 1) / TM, NT, MAIN_SMEM>>>(nbd, b_agg, b_lin);
    k_agg2<<<BATCH / 8, NT>>>(nbd, node_idx);
    k_l2f<<<BATCH / TM, NT, L2F_SMEM>>>(node_idx, b_lin, out);
}

// round 15
// speedup vs baseline: 1.2506x; 1.2506x over previous
#include <cuda_runtime.h>
#include <float.h>
#include <stdint.h>

#define N_NODES 50000
#define DEG     32
#define WID     128
#define BATCH   4096
#define NT      256
#define TM      64           // tile rows (all tensor kernels)
#define APLD    66           // A-pair ld (uint2 units)
#define WLD     130          // Ws ld (uint2 units)
#define NPAIR   64           // k-pairs per weight matrix

// ---------------- device scratch ----------------
// g_winner: slot+1 of last batch write, 0 = not in batch (zero-init; k_agg2 self-cleans)
__device__ int   g_winner[N_NODES];
__device__ float g_Mb[BATCH * WID];
__device__ float g_Fh[BATCH * WID];
__device__ float g_H1[N_NODES * WID];
__device__ float g_M2[N_NODES * WID];
__device__ float g_A2[BATCH * WID];
__device__ uint2 g_Wa2[NPAIR * WID];    // [kpair][n] bf16x2 {hi,lo}: low16 = even k
__device__ uint2 g_Wla2[NPAIR * WID];
__device__ uint2 g_Wlh2[NPAIR * WID];

// ---------------- bf16 split helpers ----------------
__device__ __forceinline__ void bfsplit2(float2 f, uint32_t& hi, uint32_t& lo) {
    uint32_t h;
    asm("cvt.rn.bf16x2.f32 %0, %1, %2;" : "=r"(h) : "f"(f.y), "f"(f.x));  // d<15:0>=f.x
    float h0 = __uint_as_float(h << 16);
    float h1 = __uint_as_float(h & 0xffff0000u);
    float r0 = f.x - h0, r1 = f.y - h1;
    asm("cvt.rn.bf16x2.f32 %0, %1, %2;" : "=r"(lo) : "f"(r1), "f"(r0));
    hi = h;
}

// m16n8k16 bf16 mma (fragment coords validated R12).
__device__ __forceinline__ void mma16(float* c, const uint32_t* a, uint32_t b0, uint32_t b1) {
    asm volatile(
        "mma.sync.aligned.m16n8k16.row.col.f32.bf16.bf16.f32 "
        "{%0,%1,%2,%3},{%4,%5,%6,%7},{%8,%9},{%0,%1,%2,%3};"
        : "+f"(c[0]), "+f"(c[1]), "+f"(c[2]), "+f"(c[3])
        : "r"(a[0]), "r"(a[1]), "r"(a[2]), "r"(a[3]), "r"(b0), "r"(b1));
}

__device__ __forceinline__ void zeroC(float C[8][4]) {
#pragma unroll
    for (int j = 0; j < 8; ++j)
#pragma unroll
        for (int c = 0; c < 4; ++c) C[j][c] = 0.f;
}

// ---------------- shared tensor GEMM: 64x128x128, 32-pair weight stages (R13) -----
// Apk: smem [row][kpair] uint2{hi,lo}, ld APLD. gW: global presplit [kpair][n].
// 8 warps: mw = warp>>1 (16 rows), nw = warp&1 (64 cols). C[8 nblk][4]. Accumulates.
__device__ __forceinline__ void tgemm(const uint2* __restrict__ Apk,
                                      const uint2* __restrict__ gW,
                                      uint2* Ws, float C[8][4],
                                      int mw, int nw, int lane) {
    const int g = lane >> 2, t = lane & 3;
#pragma unroll 1
    for (int q = 0; q < 2; ++q) {               // two 64-k stages (32 pairs each)
        for (int e = threadIdx.x; e < 32 * 64; e += NT) {
            int p = e >> 6, n2 = (e & 63) << 1;
            *(uint4*)(Ws + p * WLD + n2) = *(const uint4*)(gW + (q * 32 + p) * WID + n2);
        }
        __syncthreads();
#pragma unroll
        for (int ks = 0; ks < 4; ++ks) {        // 4 x k16 per stage
            int pk = q * 32 + ks * 8;
            const uint2* ap0 = Apk + (mw * 16 + g) * APLD + pk + t;
            const uint2* ap1 = ap0 + 8 * APLD;
            uint2 p0 = ap0[0], p1 = ap1[0], p2 = ap0[4], p3 = ap1[4];
            uint32_t ahi[4] = { p0.x, p1.x, p2.x, p3.x };
            uint32_t alo[4] = { p0.y, p1.y, p2.y, p3.y };
            const uint2* bp0 = Ws + (ks * 8 + t) * WLD + nw * 64 + g;
            const uint2* bp1 = bp0 + 4 * WLD;
#pragma unroll
            for (int j = 0; j < 8; ++j) {
                uint2 b0 = bp0[j * 8];
                uint2 b1 = bp1[j * 8];
                mma16(C[j], ahi, b0.y, b1.y);   // hi * lo
                mma16(C[j], alo, b0.x, b1.x);   // lo * hi
                mma16(C[j], ahi, b0.x, b1.x);   // hi * hi
            }
        }
        __syncthreads();
    }
}

// ---------------- setup: weight presplit + winner scatter (one kernel) ----------------
__global__ void k_prep(const float* __restrict__ W_agg, const float* __restrict__ W_lin,
                       const int* __restrict__ node_idx) {
    int t = blockIdx.x * NT + threadIdx.x;
    if (t < NPAIR * WID) {                      // kpair p: k = 2p, 2p+1
        int p = t >> 7, n = t & 127;
        uint32_t hi, lo;
        float2 fa = make_float2(W_agg[n * WID + 2 * p], W_agg[n * WID + 2 * p + 1]);
        bfsplit2(fa, hi, lo);
        g_Wa2[t] = make_uint2(hi, lo);
        float2 fh = make_float2(W_lin[n * (2 * WID) + 2 * p],
                                W_lin[n * (2 * WID) + 2 * p + 1]);
        bfsplit2(fh, hi, lo);
        g_Wlh2[t] = make_uint2(hi, lo);
        float2 fl = make_float2(W_lin[n * (2 * WID) + WID + 2 * p],
                                W_lin[n * (2 * WID) + WID + 2 * p + 1]);
        bfsplit2(fl, hi, lo);
        g_Wla2[t] = make_uint2(hi, lo);
    }
    if (t < BATCH) atomicMax(&g_winner[node_idx[t]], t + 1);   // slot+1 sentinel
}

// ---------------- batch precompute: Mb and Fh (tensor path) ----------------
#define BATCH_SMEM ((TM * APLD + 32 * WLD) * 8)
__global__ void __launch_bounds__(NT, 2)
k_batch(const float* __restrict__ feats, const float* __restrict__ b_agg) {
    extern __shared__ float sm[];
    uint2* Apk = (uint2*)sm;
    uint2* Ws  = Apk + TM * APLD;
    const int tid = threadIdx.x, lane = tid & 31, warp = tid >> 5;
    const int mw = warp >> 1, nw = warp & 1;
    const int g = lane >> 2, t4 = lane & 3;
    const int r0 = blockIdx.x * TM;

    for (int e = tid; e < TM * 64; e += NT) {
        int row = e >> 6, p = e & 63;
        float2 f = *(const float2*)(feats + (r0 + row) * WID + 2 * p);
        uint32_t hi, lo;
        bfsplit2(f, hi, lo);
        Apk[row * APLD + p] = make_uint2(hi, lo);
    }
    // (tgemm's first stage-sync orders Apk writes before reads)

    float C[8][4];
    zeroC(C);
    tgemm(Apk, g_Wa2, Ws, C, mw, nw, lane);

    float2 ba[8];
#pragma unroll
    for (int j = 0; j < 8; ++j)
        ba[j] = *(const float2*)(b_agg + nw * 64 + j * 8 + 2 * t4);
#pragma unroll
    for (int h = 0; h < 2; ++h) {
        int row = r0 + mw * 16 + g + 8 * h;
#pragma unroll
        for (int j = 0; j < 8; ++j) {
            float v0 = fmaxf(C[j][2 * h] + ba[j].x, 0.f);
            float v1 = fmaxf(C[j][2 * h + 1] + ba[j].y, 0.f);
            *(float2*)(g_Mb + row * WID + nw * 64 + j * 8 + 2 * t4) = make_float2(v0, v1);
        }
    }

    zeroC(C);
    tgemm(Apk, g_Wlh2, Ws, C, mw, nw, lane);
#pragma unroll
    for (int h = 0; h < 2; ++h) {
        int row = r0 + mw * 16 + g + 8 * h;
#pragma unroll
        for (int j = 0; j < 8; ++j)
            *(float2*)(g_Fh + row * WID + nw * 64 + j * 8 + 2 * t4) =
                make_float2(C[j][2 * h], C[j][2 * h + 1]);
    }
}

// ---------------- main fused: layer1 (agg+combine+norm) + layer2 M2 ----------------
#define MAIN_SMEM ((TM * APLD + 32 * WLD) * 8 + 2 * TM * 4)
__global__ void __launch_bounds__(NT, 3)
k_main(const int* __restrict__ nbd, const float* __restrict__ b_agg,
       const float* __restrict__ b_lin) {
    extern __shared__ float sm[];
    uint2* Apk = (uint2*)sm;                      // [64][66] {hi,lo} pairs
    uint2* Ws  = Apk + TM * APLD;                 // [32 pairs][130]
    float* ps  = (float*)(Ws + 32 * WLD);         // [2][64]
    const int tid = threadIdx.x, lane = tid & 31, warp = tid >> 5;
    const int mw = warp >> 1, nw = warp & 1;
    const int g = lane >> 2, t4 = lane & 3;
    const int r0 = blockIdx.x * TM;

    // cvec pairs: lane owns dim pairs (2*lane, 2*lane+1) and (64+2*lane, +1)
    float2 bg0 = *(const float2*)(b_agg + 2 * lane);
    float2 bg1 = *(const float2*)(b_agg + 64 + 2 * lane);
    float2 cv0 = make_float2(fmaxf(bg0.x, 0.f), fmaxf(bg0.y, 0.f));
    float2 cv1 = make_float2(fmaxf(bg1.x, 0.f), fmaxf(bg1.y, 0.f));

    // phase A: sparse max-aggregation -> split directly into Apk
#pragma unroll 1
    for (int t = warp; t < TM; t += 8) {
        int gn = r0 + t;                          // warp-uniform
        float2 a0 = make_float2(0.f, 0.f), a1 = make_float2(0.f, 0.f);
        if (gn < N_NODES) {
            int nb = nbd[gn * DEG + lane];
            int wv = g_winner[nb];                // slot+1, 0 = absent
            unsigned mask = __ballot_sync(0xffffffffu, wv > 0);
            bool plain = (mask != 0xffffffffu);
            a0 = plain ? cv0 : make_float2(-FLT_MAX, -FLT_MAX);
            a1 = plain ? cv1 : make_float2(-FLT_MAX, -FLT_MAX);
            while (mask) {
                int j = __ffs(mask) - 1;
                mask &= mask - 1;
                int wj = __shfl_sync(0xffffffffu, wv, j) - 1;
                const float* mb = g_Mb + wj * WID;
                float2 m0 = *(const float2*)(mb + 2 * lane);
                float2 m1 = *(const float2*)(mb + 64 + 2 * lane);
                a0.x = fmaxf(a0.x, m0.x); a0.y = fmaxf(a0.y, m0.y);
                a1.x = fmaxf(a1.x, m1.x); a1.y = fmaxf(a1.y, m1.y);
            }
        }
        uint32_t hi, lo;
        bfsplit2(a0, hi, lo);
        Apk[t * APLD + lane] = make_uint2(hi, lo);
        bfsplit2(a1, hi, lo);
        Apk[t * APLD + 32 + lane] = make_uint2(hi, lo);
    }
    // (tgemm's first stage-sync orders Apk writes before reads)

    // GEMM 1: agg @ Wla^T
    float C[8][4];
    zeroC(C);
    tgemm(Apk, g_Wla2, Ws, C, mw, nw, lane);

    // epilogue 1: + b_lin (+Fh winner), relu, row sumsq -> ps
    float2 bl[8];
#pragma unroll
    for (int j = 0; j < 8; ++j)
        bl[j] = *(const float2*)(b_lin + nw * 64 + j * 8 + 2 * t4);
    int warr[2];
#pragma unroll
    for (int h = 0; h < 2; ++h) {
        int rloc = mw * 16 + g + 8 * h;
        int gn = r0 + rloc;
        int w = (gn < N_NODES) ? g_winner[gn] : 0;
        warr[h] = w;
        float s = 0.f;
#pragma unroll
        for (int j = 0; j < 8; ++j) {
            float v0 = C[j][2 * h] + bl[j].x;
            float v1 = C[j][2 * h + 1] + bl[j].y;
            if (w > 0) {
                float2 f = *(const float2*)(g_Fh + (w - 1) * WID + nw * 64 + j * 8 + 2 * t4);
                v0 += f.x; v1 += f.y;
            }
            v0 = fmaxf(v0, 0.f); v1 = fmaxf(v1, 0.f);
            s += v0 * v0 + v1 * v1;
            C[j][2 * h] = v0; C[j][2 * h + 1] = v1;
        }
        s += __shfl_xor_sync(0xffffffffu, s, 1);
        s += __shfl_xor_sync(0xffffffffu, s, 2);
        if (t4 == 0) ps[nw * TM + rloc] = s;
    }
    __syncthreads();
    // normalize, stage H1 pairs into Apk, write H1 global for winner rows
#pragma unroll
    for (int h = 0; h < 2; ++h) {
        int rloc = mw * 16 + g + 8 * h;
        int gn = r0 + rloc;
        float t = ps[rloc] + ps[TM + rloc];
        float rinv = 1.0f / fmaxf(sqrtf(t), 1e-12f);
        int w = warr[h];
#pragma unroll
        for (int j = 0; j < 8; ++j) {
            float v0 = C[j][2 * h] * rinv;
            float v1 = C[j][2 * h + 1] * rinv;
            uint32_t hi, lo;
            bfsplit2(make_float2(v0, v1), hi, lo);
            Apk[rloc * APLD + nw * 32 + j * 4 + t4] = make_uint2(hi, lo);
            if (w > 0)
                *(float2*)(g_H1 + gn * WID + nw * 64 + j * 8 + 2 * t4) = make_float2(v0, v1);
        }
    }

    // GEMM 2: M2 = relu(H1 @ Wa^T + ba)
    zeroC(C);
    tgemm(Apk, g_Wa2, Ws, C, mw, nw, lane);      // stage-sync orders Apk writes

    float2 ba[8];
#pragma unroll
    for (int j = 0; j < 8; ++j)
        ba[j] = *(const float2*)(b_agg + nw * 64 + j * 8 + 2 * t4);
#pragma unroll
    for (int h = 0; h < 2; ++h) {
        int rloc = mw * 16 + g + 8 * h;
        int gn = r0 + rloc;
        if (gn >= N_NODES) continue;
#pragma unroll
        for (int j = 0; j < 8; ++j) {
            float v0 = fmaxf(C[j][2 * h] + ba[j].x, 0.f);
            float v1 = fmaxf(C[j][2 * h + 1] + ba[j].y, 0.f);
            *(float2*)(g_M2 + gn * WID + nw * 64 + j * 8 + 2 * t4) = make_float2(v0, v1);
        }
    }
}

// ---------------- layer-2 aggregation (+ winner cleanup), MLP-unrolled ----------------
__global__ void __launch_bounds__(NT, 4)
k_agg2(const int* __restrict__ nbd, const int* __restrict__ node_idx) {
    const int lane = threadIdx.x & 31, warp = threadIdx.x >> 5;
    const int slot = blockIdx.x * 8 + warp;
    const int gn = node_idx[slot];
    if (lane == 0) g_winner[gn] = 0;             // self-clean (winner last used in k_main)
    int nb = nbd[gn * DEG + lane];
    float4 acc = make_float4(-FLT_MAX, -FLT_MAX, -FLT_MAX, -FLT_MAX);
#pragma unroll
    for (int jq = 0; jq < DEG; jq += 4) {        // 4 independent row-gathers in flight
        int n0 = __shfl_sync(0xffffffffu, nb, jq + 0);
        int n1 = __shfl_sync(0xffffffffu, nb, jq + 1);
        int n2 = __shfl_sync(0xffffffffu, nb, jq + 2);
        int n3 = __shfl_sync(0xffffffffu, nb, jq + 3);
        float4 m0 = *(const float4*)(g_M2 + n0 * WID + lane * 4);
        float4 m1 = *(const float4*)(g_M2 + n1 * WID + lane * 4);
        float4 m2 = *(const float4*)(g_M2 + n2 * WID + lane * 4);
        float4 m3 = *(const float4*)(g_M2 + n3 * WID + lane * 4);
        acc.x = fmaxf(fmaxf(fmaxf(acc.x, m0.x), fmaxf(m1.x, m2.x)), m3.x);
        acc.y = fmaxf(fmaxf(fmaxf(acc.y, m0.y), fmaxf(m1.y, m2.y)), m3.y);
        acc.z = fmaxf(fmaxf(fmaxf(acc.z, m0.z), fmaxf(m1.z, m2.z)), m3.z);
        acc.w = fmaxf(fmaxf(fmaxf(acc.w, m0.w), fmaxf(m1.w, m2.w)), m3.w);
    }
    *(float4*)(g_A2 + slot * WID + lane * 4) = acc;
}

// ---------------- layer 2 final: 256-K tensor combine + norm ----------------
#define L2F_SMEM ((2 * TM * APLD + 32 * WLD) * 8 + 2 * TM * 4 + TM * 4)
__global__ void __launch_bounds__(NT, 2)
k_l2f(const int* __restrict__ node_idx, const float* __restrict__ b_lin,
      float* __restrict__ out) {
    extern __shared__ float sm[];
    uint2* A1 = (uint2*)sm;
    uint2* A2 = A1 + TM * APLD;
    uint2* Ws = A2 + TM * APLD;
    float* ps = (float*)(Ws + 32 * WLD);
    int*   nid = (int*)(ps + 2 * TM);
    const int tid = threadIdx.x, lane = tid & 31, warp = tid >> 5;
    const int mw = warp >> 1, nw = warp & 1;
    const int g = lane >> 2, t4 = lane & 3;
    const int r0 = blockIdx.x * TM;

    if (tid < TM) nid[tid] = node_idx[r0 + tid];
    __syncthreads();

    for (int e = tid; e < TM * 64; e += NT) {
        int row = e >> 6, p = e & 63;
        uint32_t hi, lo;
        float2 f = *(const float2*)(g_H1 + nid[row] * WID + 2 * p);
        bfsplit2(f, hi, lo);
        A1[row * APLD + p] = make_uint2(hi, lo);
        float2 a = *(const float2*)(g_A2 + (r0 + row) * WID + 2 * p);
        bfsplit2(a, hi, lo);
        A2[row * APLD + p] = make_uint2(hi, lo);
    }
    // (tgemm's first stage-sync orders A1/A2 writes before reads)

    float C[8][4];
    zeroC(C);
    tgemm(A1, g_Wlh2, Ws, C, mw, nw, lane);
    tgemm(A2, g_Wla2, Ws, C, mw, nw, lane);      // accumulate second K-half

    float2 bl[8];
#pragma unroll
    for (int j = 0; j < 8; ++j)
        bl[j] = *(const float2*)(b_lin + nw * 64 + j * 8 + 2 * t4);
#pragma unroll
    for (int h = 0; h < 2; ++h) {
        int rloc = mw * 16 + g + 8 * h;
        float s = 0.f;
#pragma unroll
        for (int j = 0; j < 8; ++j) {
            float v0 = fmaxf(C[j][2 * h] + bl[j].x, 0.f);
            float v1 = fmaxf(C[j][2 * h + 1] + bl[j].y, 0.f);
            s += v0 * v0 + v1 * v1;
            C[j][2 * h] = v0; C[j][2 * h + 1] = v1;
        }
        s += __shfl_xor_sync(0xffffffffu, s, 1);
        s += __shfl_xor_sync(0xffffffffu, s, 2);
        if (t4 == 0) ps[nw * TM + rloc] = s;
    }
    __syncthreads();
#pragma unroll
    for (int h = 0; h < 2; ++h) {
        int rloc = mw * 16 + g + 8 * h;
        float t = ps[rloc] + ps[TM + rloc];
        float rinv = 1.0f / fmaxf(sqrtf(t), 1e-12f);
#pragma unroll
        for (int j = 0; j < 8; ++j) {
            float v0 = C[j][2 * h] * rinv;
            float v1 = C[j][2 * h + 1] * rinv;
            *(float2*)(out + (r0 + rloc) * WID + nw * 64 + j * 8 + 2 * t4) =
                make_float2(v0, v1);
        }
    }
}

// ---------------- launch ----------------
extern "C" void kernel_launch(void* const* d_in, const int* in_sizes, int n_in,
                              void* d_out, int out_size) {
    const int*   nbd      = (const int*)d_in[0];
    const int*   node_idx = (const int*)d_in[1];
    const float* feats    = (const float*)d_in[2];
    const float* W_agg    = (const float*)d_in[3];
    const float* b_agg    = (const float*)d_in[4];
    const float* W_lin    = (const float*)d_in[5];
    const float* b_lin    = (const float*)d_in[6];
    float* out = (float*)d_out;

    cudaFuncSetAttribute(k_batch, cudaFuncAttributeMaxDynamicSharedMemorySize, BATCH_SMEM);
    cudaFuncSetAttribute(k_main,  cudaFuncAttributeMaxDynamicSharedMemorySize, MAIN_SMEM);
    cudaFuncSetAttribute(k_l2f,   cudaFuncAttributeMaxDynamicSharedMemorySize, L2F_SMEM);

    k_prep<<<(NPAIR * WID + NT - 1) / NT, NT>>>(W_agg, W_lin, node_idx);
    k_batch<<<BATCH / TM, NT, BATCH_SMEM>>>(feats, b_agg);
    k_main<<<(N_NODES + TM - 1) / TM, NT, MAIN_SMEM>>>(nbd, b_agg, b_lin);
    k_agg2<<<BATCH / 8, NT>>>(nbd, node_idx);
    k_l2f<<<BATCH / TM, NT, L2F_SMEM>>>(node_idx, b_lin, out);
}

// round 16
// speedup vs baseline: 1.2762x; 1.0205x over previous
#include <cuda_runtime.h>
#include <float.h>
#include <stdint.h>

#define N_NODES 50000
#define DEG     32
#define WID     128
#define BATCH   4096
#define NT      256
#define TM      64           // tile rows (all tensor kernels)
#define APLD    66           // A-pair ld (uint2 units)
#define WLD     130          // Ws ld (uint2 units)
#define NPAIR   64           // k-pairs per weight matrix

// ---------------- device scratch ----------------
// g_winner: slot+1 of last batch write, 0 = not in batch (zero-init; k_agg2 self-cleans)
__device__ int   g_winner[N_NODES];
__device__ float g_Mb[BATCH * WID];
__device__ float g_Fh[BATCH * WID];
__device__ float g_H1[N_NODES * WID];
__device__ float g_M2[N_NODES * WID];
__device__ float g_A2[BATCH * WID];
__device__ uint2 g_Wa2[NPAIR * WID];    // [kpair][n] bf16x2 {hi,lo}: low16 = even k
__device__ uint2 g_Wla2[NPAIR * WID];
__device__ uint2 g_Wlh2[NPAIR * WID];

// ---------------- bf16 split helpers ----------------
__device__ __forceinline__ void bfsplit2(float2 f, uint32_t& hi, uint32_t& lo) {
    uint32_t h;
    asm("cvt.rn.bf16x2.f32 %0, %1, %2;" : "=r"(h) : "f"(f.y), "f"(f.x));  // d<15:0>=f.x
    float h0 = __uint_as_float(h << 16);
    float h1 = __uint_as_float(h & 0xffff0000u);
    float r0 = f.x - h0, r1 = f.y - h1;
    asm("cvt.rn.bf16x2.f32 %0, %1, %2;" : "=r"(lo) : "f"(r1), "f"(r0));
    hi = h;
}

// m16n8k16 bf16 mma (fragment coords validated R12).
__device__ __forceinline__ void mma16(float* c, const uint32_t* a, uint32_t b0, uint32_t b1) {
    asm volatile(
        "mma.sync.aligned.m16n8k16.row.col.f32.bf16.bf16.f32 "
        "{%0,%1,%2,%3},{%4,%5,%6,%7},{%8,%9},{%0,%1,%2,%3};"
        : "+f"(c[0]), "+f"(c[1]), "+f"(c[2]), "+f"(c[3])
        : "r"(a[0]), "r"(a[1]), "r"(a[2]), "r"(a[3]), "r"(b0), "r"(b1));
}

__device__ __forceinline__ void zeroC(float C[8][4]) {
#pragma unroll
    for (int j = 0; j < 8; ++j)
#pragma unroll
        for (int c = 0; c < 4; ++c) C[j][c] = 0.f;
}

// ---------------- shared tensor GEMM: 64x128x128, 32-pair weight stages ----------------
// Apk: smem [row][kpair] uint2{hi,lo}, ld APLD. gW: global presplit [kpair][n].
// 8 warps: mw = warp>>1 (16 rows), nw = warp&1 (64 cols). C[8 nblk][4]. Accumulates.
__device__ __forceinline__ void tgemm(const uint2* __restrict__ Apk,
                                      const uint2* __restrict__ gW,
                                      uint2* Ws, float C[8][4],
                                      int mw, int nw, int lane) {
    const int g = lane >> 2, t = lane & 3;
#pragma unroll 1
    for (int q = 0; q < 2; ++q) {               // two 64-k stages (32 pairs each)
        for (int e = threadIdx.x; e < 32 * 64; e += NT) {
            int p = e >> 6, n2 = (e & 63) << 1;
            *(uint4*)(Ws + p * WLD + n2) = *(const uint4*)(gW + (q * 32 + p) * WID + n2);
        }
        __syncthreads();
#pragma unroll
        for (int ks = 0; ks < 4; ++ks) {        // 4 x k16 per stage
            int pk = q * 32 + ks * 8;
            const uint2* ap0 = Apk + (mw * 16 + g) * APLD + pk + t;
            const uint2* ap1 = ap0 + 8 * APLD;
            uint2 p0 = ap0[0], p1 = ap1[0], p2 = ap0[4], p3 = ap1[4];
            uint32_t ahi[4] = { p0.x, p1.x, p2.x, p3.x };
            uint32_t alo[4] = { p0.y, p1.y, p2.y, p3.y };
            const uint2* bp0 = Ws + (ks * 8 + t) * WLD + nw * 64 + g;
            const uint2* bp1 = bp0 + 4 * WLD;
#pragma unroll
            for (int j = 0; j < 8; ++j) {
                uint2 b0 = bp0[j * 8];
                uint2 b1 = bp1[j * 8];
                mma16(C[j], ahi, b0.y, b1.y);   // hi * lo
                mma16(C[j], alo, b0.x, b1.x);   // lo * hi
                mma16(C[j], ahi, b0.x, b1.x);   // hi * hi
            }
        }
        __syncthreads();
    }
}

// ---------------- setup: weight presplit + winner scatter (one kernel) ----------------
__global__ void k_prep(const float* __restrict__ W_agg, const float* __restrict__ W_lin,
                       const int* __restrict__ node_idx) {
    int t = blockIdx.x * NT + threadIdx.x;
    if (t < NPAIR * WID) {                      // kpair p: k = 2p, 2p+1
        int p = t >> 7, n = t & 127;
        uint32_t hi, lo;
        float2 fa = make_float2(W_agg[n * WID + 2 * p], W_agg[n * WID + 2 * p + 1]);
        bfsplit2(fa, hi, lo);
        g_Wa2[t] = make_uint2(hi, lo);
        float2 fh = make_float2(W_lin[n * (2 * WID) + 2 * p],
                                W_lin[n * (2 * WID) + 2 * p + 1]);
        bfsplit2(fh, hi, lo);
        g_Wlh2[t] = make_uint2(hi, lo);
        float2 fl = make_float2(W_lin[n * (2 * WID) + WID + 2 * p],
                                W_lin[n * (2 * WID) + WID + 2 * p + 1]);
        bfsplit2(fl, hi, lo);
        g_Wla2[t] = make_uint2(hi, lo);
    }
    if (t < BATCH) atomicMax(&g_winner[node_idx[t]], t + 1);   // slot+1 sentinel
}

// ---------------- batch precompute: Mb / Fh, one GEMM per CTA (2-way split) ----------
#define BATCH_SMEM ((TM * APLD + 32 * WLD) * 8)
__global__ void __launch_bounds__(NT, 2)
k_batch(const float* __restrict__ feats, const float* __restrict__ b_agg) {
    extern __shared__ float sm[];
    uint2* Apk = (uint2*)sm;
    uint2* Ws  = Apk + TM * APLD;
    const int tid = threadIdx.x, lane = tid & 31, warp = tid >> 5;
    const int mw = warp >> 1, nw = warp & 1;
    const int g = lane >> 2, t4 = lane & 3;
    const int r0 = (blockIdx.x >> 1) * TM;
    const int sel = blockIdx.x & 1;             // 0: Mb (Wa+bias+relu), 1: Fh (Wlh)

    for (int e = tid; e < TM * 64; e += NT) {
        int row = e >> 6, p = e & 63;
        float2 f = *(const float2*)(feats + (r0 + row) * WID + 2 * p);
        uint32_t hi, lo;
        bfsplit2(f, hi, lo);
        Apk[row * APLD + p] = make_uint2(hi, lo);
    }
    // (tgemm's first stage-sync orders Apk writes before reads)

    float C[8][4];
    zeroC(C);
    if (sel == 0) {
        tgemm(Apk, g_Wa2, Ws, C, mw, nw, lane);
        float2 ba[8];
#pragma unroll
        for (int j = 0; j < 8; ++j)
            ba[j] = *(const float2*)(b_agg + nw * 64 + j * 8 + 2 * t4);
#pragma unroll
        for (int h = 0; h < 2; ++h) {
            int row = r0 + mw * 16 + g + 8 * h;
#pragma unroll
            for (int j = 0; j < 8; ++j) {
                float v0 = fmaxf(C[j][2 * h] + ba[j].x, 0.f);
                float v1 = fmaxf(C[j][2 * h + 1] + ba[j].y, 0.f);
                *(float2*)(g_Mb + row * WID + nw * 64 + j * 8 + 2 * t4) = make_float2(v0, v1);
            }
        }
    } else {
        tgemm(Apk, g_Wlh2, Ws, C, mw, nw, lane);
#pragma unroll
        for (int h = 0; h < 2; ++h) {
            int row = r0 + mw * 16 + g + 8 * h;
#pragma unroll
            for (int j = 0; j < 8; ++j)
                *(float2*)(g_Fh + row * WID + nw * 64 + j * 8 + 2 * t4) =
                    make_float2(C[j][2 * h], C[j][2 * h + 1]);
        }
    }
}

// ---------------- main fused: layer1 (agg+combine+norm) + layer2 M2 ----------------
#define MAIN_SMEM ((TM * APLD + 32 * WLD) * 8 + 2 * TM * 4)
__global__ void __launch_bounds__(NT, 3)
k_main(const int* __restrict__ nbd, const float* __restrict__ b_agg,
       const float* __restrict__ b_lin) {
    extern __shared__ float sm[];
    uint2* Apk = (uint2*)sm;                      // [64][66] {hi,lo} pairs
    uint2* Ws  = Apk + TM * APLD;                 // [32 pairs][130]
    float* ps  = (float*)(Ws + 32 * WLD);         // [2][64]
    const int tid = threadIdx.x, lane = tid & 31, warp = tid >> 5;
    const int mw = warp >> 1, nw = warp & 1;
    const int g = lane >> 2, t4 = lane & 3;
    const int r0 = blockIdx.x * TM;

    // cvec pairs: lane owns dim pairs (2*lane, 2*lane+1) and (64+2*lane, +1)
    float2 bg0 = *(const float2*)(b_agg + 2 * lane);
    float2 bg1 = *(const float2*)(b_agg + 64 + 2 * lane);
    float2 cv0 = make_float2(fmaxf(bg0.x, 0.f), fmaxf(bg0.y, 0.f));
    float2 cv1 = make_float2(fmaxf(bg1.x, 0.f), fmaxf(bg1.y, 0.f));

    // phase A: sparse max-aggregation -> split directly into Apk.
    // MLP: batch all 8 nbd loads, then all 8 winner gathers (independent chains).
    int nbv[8], wvv[8];
#pragma unroll
    for (int p = 0; p < 8; ++p) {
        int gn = r0 + warp + p * 8;
        nbv[p] = (gn < N_NODES) ? nbd[gn * DEG + lane] : 0;
    }
#pragma unroll
    for (int p = 0; p < 8; ++p) wvv[p] = g_winner[nbv[p]];   // slot+1, 0 = absent
#pragma unroll 1
    for (int p = 0; p < 8; ++p) {
        int t = warp + p * 8;
        int gn = r0 + t;                          // warp-uniform
        float2 a0 = make_float2(0.f, 0.f), a1 = make_float2(0.f, 0.f);
        if (gn < N_NODES) {
            int wv = wvv[p];
            unsigned mask = __ballot_sync(0xffffffffu, wv > 0);
            bool plain = (mask != 0xffffffffu);
            a0 = plain ? cv0 : make_float2(-FLT_MAX, -FLT_MAX);
            a1 = plain ? cv1 : make_float2(-FLT_MAX, -FLT_MAX);
            while (mask) {
                int j = __ffs(mask) - 1;
                mask &= mask - 1;
                int wj = __shfl_sync(0xffffffffu, wv, j) - 1;
                const float* mb = g_Mb + wj * WID;
                float2 m0 = *(const float2*)(mb + 2 * lane);
                float2 m1 = *(const float2*)(mb + 64 + 2 * lane);
                a0.x = fmaxf(a0.x, m0.x); a0.y = fmaxf(a0.y, m0.y);
                a1.x = fmaxf(a1.x, m1.x); a1.y = fmaxf(a1.y, m1.y);
            }
        }
        uint32_t hi, lo;
        bfsplit2(a0, hi, lo);
        Apk[t * APLD + lane] = make_uint2(hi, lo);
        bfsplit2(a1, hi, lo);
        Apk[t * APLD + 32 + lane] = make_uint2(hi, lo);
    }
    // (tgemm's first stage-sync orders Apk writes before reads)

    // GEMM 1: agg @ Wla^T
    float C[8][4];
    zeroC(C);
    tgemm(Apk, g_Wla2, Ws, C, mw, nw, lane);

    // epilogue 1: + b_lin (+Fh winner), relu, row sumsq -> ps
    float2 bl[8];
#pragma unroll
    for (int j = 0; j < 8; ++j)
        bl[j] = *(const float2*)(b_lin + nw * 64 + j * 8 + 2 * t4);
    int warr[2];
#pragma unroll
    for (int h = 0; h < 2; ++h) {
        int rloc = mw * 16 + g + 8 * h;
        int gn = r0 + rloc;
        int w = (gn < N_NODES) ? g_winner[gn] : 0;
        warr[h] = w;
        float s = 0.f;
#pragma unroll
        for (int j = 0; j < 8; ++j) {
            float v0 = C[j][2 * h] + bl[j].x;
            float v1 = C[j][2 * h + 1] + bl[j].y;
            if (w > 0) {
                float2 f = *(const float2*)(g_Fh + (w - 1) * WID + nw * 64 + j * 8 + 2 * t4);
                v0 += f.x; v1 += f.y;
            }
            v0 = fmaxf(v0, 0.f); v1 = fmaxf(v1, 0.f);
            s += v0 * v0 + v1 * v1;
            C[j][2 * h] = v0; C[j][2 * h + 1] = v1;
        }
        s += __shfl_xor_sync(0xffffffffu, s, 1);
        s += __shfl_xor_sync(0xffffffffu, s, 2);
        if (t4 == 0) ps[nw * TM + rloc] = s;
    }
    __syncthreads();
    // normalize, stage H1 pairs into Apk, write H1 global for winner rows
#pragma unroll
    for (int h = 0; h < 2; ++h) {
        int rloc = mw * 16 + g + 8 * h;
        int gn = r0 + rloc;
        float t = ps[rloc] + ps[TM + rloc];
        float rinv = 1.0f / fmaxf(sqrtf(t), 1e-12f);
        int w = warr[h];
#pragma unroll
        for (int j = 0; j < 8; ++j) {
            float v0 = C[j][2 * h] * rinv;
            float v1 = C[j][2 * h + 1] * rinv;
            uint32_t hi, lo;
            bfsplit2(make_float2(v0, v1), hi, lo);
            Apk[rloc * APLD + nw * 32 + j * 4 + t4] = make_uint2(hi, lo);
            if (w > 0)
                *(float2*)(g_H1 + gn * WID + nw * 64 + j * 8 + 2 * t4) = make_float2(v0, v1);
        }
    }

    // GEMM 2: M2 = relu(H1 @ Wa^T + ba)
    zeroC(C);
    tgemm(Apk, g_Wa2, Ws, C, mw, nw, lane);      // stage-sync orders Apk writes

    float2 ba[8];
#pragma unroll
    for (int j = 0; j < 8; ++j)
        ba[j] = *(const float2*)(b_agg + nw * 64 + j * 8 + 2 * t4);
#pragma unroll
    for (int h = 0; h < 2; ++h) {
        int rloc = mw * 16 + g + 8 * h;
        int gn = r0 + rloc;
        if (gn >= N_NODES) continue;
#pragma unroll
        for (int j = 0; j < 8; ++j) {
            float v0 = fmaxf(C[j][2 * h] + ba[j].x, 0.f);
            float v1 = fmaxf(C[j][2 * h + 1] + ba[j].y, 0.f);
            *(float2*)(g_M2 + gn * WID + nw * 64 + j * 8 + 2 * t4) = make_float2(v0, v1);
        }
    }
}

// ---------------- layer-2 aggregation (+ winner cleanup), MLP-unrolled ----------------
__global__ void __launch_bounds__(NT, 4)
k_agg2(const int* __restrict__ nbd, const int* __restrict__ node_idx) {
    const int lane = threadIdx.x & 31, warp = threadIdx.x >> 5;
    const int slot = blockIdx.x * 8 + warp;
    const int gn = node_idx[slot];
    if (lane == 0) g_winner[gn] = 0;             // self-clean (winner last used in k_main)
    int nb = nbd[gn * DEG + lane];
    float4 acc = make_float4(-FLT_MAX, -FLT_MAX, -FLT_MAX, -FLT_MAX);
#pragma unroll
    for (int jq = 0; jq < DEG; jq += 4) {        // 4 independent row-gathers in flight
        int n0 = __shfl_sync(0xffffffffu, nb, jq + 0);
        int n1 = __shfl_sync(0xffffffffu, nb, jq + 1);
        int n2 = __shfl_sync(0xffffffffu, nb, jq + 2);
        int n3 = __shfl_sync(0xffffffffu, nb, jq + 3);
        float4 m0 = *(const float4*)(g_M2 + n0 * WID + lane * 4);
        float4 m1 = *(const float4*)(g_M2 + n1 * WID + lane * 4);
        float4 m2 = *(const float4*)(g_M2 + n2 * WID + lane * 4);
        float4 m3 = *(const float4*)(g_M2 + n3 * WID + lane * 4);
        acc.x = fmaxf(fmaxf(fmaxf(acc.x, m0.x), fmaxf(m1.x, m2.x)), m3.x);
        acc.y = fmaxf(fmaxf(fmaxf(acc.y, m0.y), fmaxf(m1.y, m2.y)), m3.y);
        acc.z = fmaxf(fmaxf(fmaxf(acc.z, m0.z), fmaxf(m1.z, m2.z)), m3.z);
        acc.w = fmaxf(fmaxf(fmaxf(acc.w, m0.w), fmaxf(m1.w, m2.w)), m3.w);
    }
    *(float4*)(g_A2 + slot * WID + lane * 4) = acc;
}

// ---------------- layer 2 final: 256-K tensor combine + norm ----------------
#define L2F_SMEM ((2 * TM * APLD + 32 * WLD) * 8 + 2 * TM * 4 + TM * 4)
__global__ void __launch_bounds__(NT, 2)
k_l2f(const int* __restrict__ node_idx, const float* __restrict__ b_lin,
      float* __restrict__ out) {
    extern __shared__ float sm[];
    uint2* A1 = (uint2*)sm;
    uint2* A2 = A1 + TM * APLD;
    uint2* Ws = A2 + TM * APLD;
    float* ps = (float*)(Ws + 32 * WLD);
    int*   nid = (int*)(ps + 2 * TM);
    const int tid = threadIdx.x, lane = tid & 31, warp = tid >> 5;
    const int mw = warp >> 1, nw = warp & 1;
    const int g = lane >> 2, t4 = lane & 3;
    const int r0 = blockIdx.x * TM;

    if (tid < TM) nid[tid] = node_idx[r0 + tid];
    __syncthreads();

    for (int e = tid; e < TM * 64; e += NT) {
        int row = e >> 6, p = e & 63;
        uint32_t hi, lo;
        float2 f = *(const float2*)(g_H1 + nid[row] * WID + 2 * p);
        bfsplit2(f, hi, lo);
        A1[row * APLD + p] = make_uint2(hi, lo);
        float2 a = *(const float2*)(g_A2 + (r0 + row) * WID + 2 * p);
        bfsplit2(a, hi, lo);
        A2[row * APLD + p] = make_uint2(hi, lo);
    }
    // (tgemm's first stage-sync orders A1/A2 writes before reads)

    float C[8][4];
    zeroC(C);
    tgemm(A1, g_Wlh2, Ws, C, mw, nw, lane);
    tgemm(A2, g_Wla2, Ws, C, mw, nw, lane);      // accumulate second K-half

    float2 bl[8];
#pragma unroll
    for (int j = 0; j < 8; ++j)
        bl[j] = *(const float2*)(b_lin + nw * 64 + j * 8 + 2 * t4);
#pragma unroll
    for (int h = 0; h < 2; ++h) {
        int rloc = mw * 16 + g + 8 * h;
        float s = 0.f;
#pragma unroll
        for (int j = 0; j < 8; ++j) {
            float v0 = fmaxf(C[j][2 * h] + bl[j].x, 0.f);
            float v1 = fmaxf(C[j][2 * h + 1] + bl[j].y, 0.f);
            s += v0 * v0 + v1 * v1;
            C[j][2 * h] = v0; C[j][2 * h + 1] = v1;
        }
        s += __shfl_xor_sync(0xffffffffu, s, 1);
        s += __shfl_xor_sync(0xffffffffu, s, 2);
        if (t4 == 0) ps[nw * TM + rloc] = s;
    }
    __syncthreads();
#pragma unroll
    for (int h = 0; h < 2; ++h) {
        int rloc = mw * 16 + g + 8 * h;
        float t = ps[rloc] + ps[TM + rloc];
        float rinv = 1.0f / fmaxf(sqrtf(t), 1e-12f);
#pragma unroll
        for (int j = 0; j < 8; ++j) {
            float v0 = C[j][2 * h] * rinv;
            float v1 = C[j][2 * h + 1] * rinv;
            *(float2*)(out + (r0 + rloc) * WID + nw * 64 + j * 8 + 2 * t4) =
                make_float2(v0, v1);
        }
    }
}

// ---------------- launch ----------------
extern "C" void kernel_launch(void* const* d_in, const int* in_sizes, int n_in,
                              void* d_out, int out_size) {
    const int*   nbd      = (const int*)d_in[0];
    const int*   node_idx = (const int*)d_in[1];
    const float* feats    = (const float*)d_in[2];
    const float* W_agg    = (const float*)d_in[3];
    const float* b_agg    = (const float*)d_in[4];
    const float* W_lin    = (const float*)d_in[5];
    const float* b_lin    = (const float*)d_in[6];
    float* out = (float*)d_out;

    cudaFuncSetAttribute(k_batch, cudaFuncAttributeMaxDynamicSharedMemorySize, BATCH_SMEM);
    cudaFuncSetAttribute(k_main,  cudaFuncAttributeMaxDynamicSharedMemorySize, MAIN_SMEM);
    cudaFuncSetAttribute(k_l2f,   cudaFuncAttributeMaxDynamicSharedMemorySize, L2F_SMEM);

    k_prep<<<(NPAIR * WID + NT - 1) / NT, NT>>>(W_agg, W_lin, node_idx);
    k_batch<<<(BATCH / TM) * 2, NT, BATCH_SMEM>>>(feats, b_agg);
    k_main<<<(N_NODES + TM - 1) / TM, NT, MAIN_SMEM>>>(nbd, b_agg, b_lin);
    k_agg2<<<BATCH / 8, NT>>>(nbd, node_idx);
    k_l2f<<<BATCH / TM, NT, L2F_SMEM>>>(node_idx, b_lin, out);
}